// round 1
// baseline (speedup 1.0000x reference)
#include <cuda_runtime.h>
#include <math.h>

// Problem constants
#define BB 2
#define TT 4096
#define CC 1024
#define NH 8
#define DD 128
#define CHK 64
#define NCHUNK 64            // T / CHK
#define NCID 1024            // BB*NH*NCHUNK

// ---------------- scratch (device globals; no allocation allowed) ----------------
__device__ float g_qkvz[(size_t)BB*TT*4096];     // x @ W_qkvz      (B,T,8,512)
__device__ float g_ba[(size_t)BB*TT*16];         // x @ W_ba
__device__ float g_conv[(size_t)BB*TT*3072];     // conv+silu [q|k|v]
__device__ float g_g[(size_t)BB*TT*NH];
__device__ float g_beta[(size_t)BB*TT*NH];
__device__ float g_P[(size_t)NCID*64*128];       // qeff - attn@k_cum
__device__ float g_L[(size_t)NCID*64*128];       // attn@v_new
__device__ float g_M[(size_t)NCID*128*128];      // keff^T @ k_cum
__device__ float g_U[(size_t)NCID*128*128];      // keff^T @ v_new
__device__ float g_egl[NCID];                    // exp(g_last)
__device__ float g_core[(size_t)BB*TT*NH*DD];    // delta-rule output
__device__ float g_hbuf[(size_t)BB*TT*1024];     // post-norm, pre out-proj

// ---------------- generic SGEMM: C(MxN) = A(MxK) @ B(KxN), all row-major --------
// M,N multiples of 128; K multiple of 16.
__global__ __launch_bounds__(256) void sgemm128(int M, int N, int K,
        const float* __restrict__ A, const float* __restrict__ Bm, float* __restrict__ Cm)
{
    __shared__ float As[16][128];
    __shared__ float Bs[16][128];
    int tid = threadIdx.x;
    int brow = blockIdx.y * 128, bcol = blockIdx.x * 128;
    int trow = (tid / 16) * 8, tcol = (tid % 16) * 8;
    float acc[8][8];
#pragma unroll
    for (int i = 0; i < 8; i++)
#pragma unroll
        for (int j = 0; j < 8; j++) acc[i][j] = 0.f;

    for (int k0 = 0; k0 < K; k0 += 16) {
#pragma unroll
        for (int ld = 0; ld < 2; ld++) {
            int idx = tid + ld * 256;
            int ar = idx >> 2, ak = (idx & 3) * 4;
            float4 av = *(const float4*)(A + (size_t)(brow + ar) * K + (k0 + ak));
            As[ak + 0][ar] = av.x; As[ak + 1][ar] = av.y;
            As[ak + 2][ar] = av.z; As[ak + 3][ar] = av.w;
            int bk = idx >> 5, bn = (idx & 31) * 4;
            *(float4*)(&Bs[bk][bn]) = *(const float4*)(Bm + (size_t)(k0 + bk) * N + (bcol + bn));
        }
        __syncthreads();
#pragma unroll
        for (int kk = 0; kk < 16; kk++) {
            float4 a0 = *(const float4*)(&As[kk][trow]);
            float4 a1 = *(const float4*)(&As[kk][trow + 4]);
            float4 b0 = *(const float4*)(&Bs[kk][tcol]);
            float4 b1 = *(const float4*)(&Bs[kk][tcol + 4]);
            float ra[8] = {a0.x, a0.y, a0.z, a0.w, a1.x, a1.y, a1.z, a1.w};
            float rb[8] = {b0.x, b0.y, b0.z, b0.w, b1.x, b1.y, b1.z, b1.w};
#pragma unroll
            for (int i = 0; i < 8; i++)
#pragma unroll
                for (int j = 0; j < 8; j++) acc[i][j] += ra[i] * rb[j];
        }
        __syncthreads();
    }
#pragma unroll
    for (int i = 0; i < 8; i++)
#pragma unroll
        for (int j = 0; j < 8; j += 4)
            *(float4*)(Cm + (size_t)(brow + trow + i) * N + bcol + tcol + j) =
                make_float4(acc[i][j], acc[i][j + 1], acc[i][j + 2], acc[i][j + 3]);
}

// ---------------- ba = x @ W_ba (N = 16) ----------------------------------------
__global__ __launch_bounds__(256) void ba_kernel(const float* __restrict__ x,
        const float* __restrict__ Wba, float* __restrict__ out)
{
    int bt = blockIdx.x;
    __shared__ float xs[1024];
    const float* xrow = x + (size_t)bt * 1024;
    for (int i = threadIdx.x; i < 256; i += 256)
        ((float4*)xs)[i] = ((const float4*)xrow)[i];
    __syncthreads();
    int o = threadIdx.x >> 4, p = threadIdx.x & 15;
    float acc = 0.f;
    for (int k = p; k < 1024; k += 16) acc += xs[k] * Wba[(size_t)k * 16 + o];
    acc += __shfl_down_sync(0xffffffffu, acc, 8);
    acc += __shfl_down_sync(0xffffffffu, acc, 4);
    acc += __shfl_down_sync(0xffffffffu, acc, 2);
    acc += __shfl_down_sync(0xffffffffu, acc, 1);
    if (p == 0) out[(size_t)bt * 16 + o] = acc;
}

// ---------------- causal depthwise conv (K=4) + silu ----------------------------
__global__ __launch_bounds__(256) void conv_silu_kernel(const float* __restrict__ qkvz,
        const float* __restrict__ cw, float* __restrict__ out)
{
    int idx = blockIdx.x * 256 + threadIdx.x;        // over B*T*3072 (fits int)
    int ch = idx % 3072;
    int btrow = idx / 3072;                           // global row b*T + t
    int t = btrow & (TT - 1);
    int part = ch >> 10;                              // 0=q,1=k,2=v
    int hc = (ch & 1023) >> 7;
    int d = ch & 127;
    int po = (part == 0) ? 0 : (part == 1) ? 128 : 256;
    float acc = 0.f;
#pragma unroll
    for (int j = 0; j < 4; j++) {
        int tt2 = t - 3 + j;
        if (tt2 >= 0) {
            float v = qkvz[(((size_t)(btrow - 3 + j)) * 8 + hc) * 512 + po + d];
            acc += v * cw[ch * 4 + j];
        }
    }
    out[(size_t)idx] = acc / (1.f + __expf(-acc));    // silu
}

// ---------------- g, beta --------------------------------------------------------
__global__ __launch_bounds__(256) void gbeta_kernel(const float* __restrict__ ba,
        const float* __restrict__ dtb, const float* __restrict__ Alog,
        float* __restrict__ g, float* __restrict__ beta)
{
    int idx = blockIdx.x * 256 + threadIdx.x;         // B*T*8
    int h = idx & 7;
    int bt = idx >> 3;
    float bv = ba[(size_t)bt * 16 + h * 2];
    float av = ba[(size_t)bt * 16 + h * 2 + 1];
    beta[idx] = 1.f / (1.f + expf(-bv));
    float xx = av + dtb[h];
    float sp = (xx > 20.f) ? xx : log1pf(expf(xx));
    g[idx] = -expf(Alog[h]) * sp;
}

// ---------------- Phase A: per-chunk local operators ----------------------------
#define KQ 129                                       // padded row stride for q,k
#define PA_SMEM ((64*KQ*2 + 64*256 + 64*64 + 256) * 4)

__global__ __launch_bounds__(256) void phaseA_kernel(const float* __restrict__ conv,
        const float* __restrict__ gbuf, const float* __restrict__ betabuf,
        float* __restrict__ Pout, float* __restrict__ Lout,
        float* __restrict__ Mout, float* __restrict__ Uout, float* __restrict__ eglout)
{
    extern __shared__ float sm[];
    float* qs  = sm;                  // 64 x 129
    float* ks  = qs + 64 * KQ;        // 64 x 129
    float* ws  = ks + 64 * KQ;        // 64 x 256  [v*beta | k*beta*e^gc]
    float* As  = ws + 64 * 256;       // 64 x 64
    float* gc  = As + 64 * 64;        // 64
    float* egc = gc + 64;             // exp(gc)
    float* egr = egc + 64;            // exp(g_last - gc)
    float* bts = egr + 64;            // beta

    int cid = blockIdx.x;
    int n = cid & 63, bh = cid >> 6, h = bh & 7, b = bh >> 3;
    int tid = threadIdx.x;
    int t0 = n * 64;

    if (tid < 64) {
        int t = t0 + tid;
        gc[tid]  = gbuf[((size_t)(b * TT + t)) * 8 + h];
        bts[tid] = betabuf[((size_t)(b * TT + t)) * 8 + h];
    }
    __syncthreads();
    if (tid == 0) {
        float c = 0.f;
        for (int i = 0; i < 64; i++) { c += gc[i]; gc[i] = c; }
    }
    __syncthreads();
    if (tid < 64) {
        egc[tid] = __expf(gc[tid]);
        egr[tid] = __expf(gc[63] - gc[tid]);
    }
    __syncthreads();

    // load + l2norm q,k; init ws
    {
        int warp = tid >> 5, lane = tid & 31;
        for (int r = warp; r < 64; r += 8) {
            int t = t0 + r;
            const float* base = conv + ((size_t)(b * TT + t)) * 3072 + h * 128;
            float qv[4], kv[4];
            float ssq = 0.f, ssk = 0.f;
#pragma unroll
            for (int u = 0; u < 4; u++) {
                qv[u] = base[lane + u * 32];
                kv[u] = base[1024 + lane + u * 32];
                ssq += qv[u] * qv[u];
                ssk += kv[u] * kv[u];
            }
#pragma unroll
            for (int off = 16; off; off >>= 1) {
                ssq += __shfl_xor_sync(0xffffffffu, ssq, off);
                ssk += __shfl_xor_sync(0xffffffffu, ssk, off);
            }
            float rq = rsqrtf(ssq + 1e-6f) * 0.08838834764831845f;  // * DK^-0.5
            float rk = rsqrtf(ssk + 1e-6f);
            float bbv = bts[r], egv = egc[r];
#pragma unroll
            for (int u = 0; u < 4; u++) {
                int d = lane + u * 32;
                qs[r * KQ + d] = qv[u] * rq;
                float kn = kv[u] * rk;
                ks[r * KQ + d] = kn;
                ws[r * 256 + d]       = base[2048 + d] * bbv;   // v * beta
                ws[r * 256 + 128 + d] = kn * bbv * egv;          // k*beta*e^gc
            }
        }
    }
    __syncthreads();

    // A[i][j] = beta_i (k_i . k_j) exp(gc_i - gc_j), j < i (strict lower)
    {
        int i = tid >> 2, jg = tid & 3;
        for (int jj = 0; jj < 16; jj++) {
            int j = jg + jj * 4;
            float acc = 0.f;
            if (j < i) {
#pragma unroll 8
                for (int d = 0; d < 128; d++) acc += ks[i * KQ + d] * ks[j * KQ + d];
                acc *= bts[i] * __expf(gc[i] - gc[j]);
            }
            As[i * 64 + j] = acc;
        }
    }
    __syncthreads();

    // forward substitution: ws <- (I+A)^{-1} ws (each thread owns one column)
    {
        int c = tid;
        for (int i = 1; i < 64; i++) {
            float acc = 0.f;
            for (int j = 0; j < i; j++) acc += As[i * 64 + j] * ws[j * 256 + c];
            ws[i * 256 + c] -= acc;
        }
    }
    __syncthreads();

    // attn[i][j] = (q_i . k_j) exp(gc_i - gc_j), j <= i  (overwrite As)
    {
        int i = tid >> 2, jg = tid & 3;
        for (int jj = 0; jj < 16; jj++) {
            int j = jg + jj * 4;
            float acc = 0.f;
            if (j <= i) {
#pragma unroll 8
                for (int d = 0; d < 128; d++) acc += qs[i * KQ + d] * ks[j * KQ + d];
                acc *= __expf(gc[i] - gc[j]);
            }
            As[i * 64 + j] = acc;
        }
    }
    __syncthreads();

    // L = attn @ v_new ; P = q*e^gc - attn @ k_cum
    {
        int c = tid & 127, ig = tid >> 7;
        for (int r = 0; r < 32; r++) {
            int i = ig * 32 + r;
            float accL = 0.f, accP = 0.f;
            for (int j = 0; j <= i; j++) {
                float a = As[i * 64 + j];
                accL += a * ws[j * 256 + c];
                accP += a * ws[j * 256 + 128 + c];
            }
            Lout[((size_t)cid * 64 + i) * 128 + c] = accL;
            Pout[((size_t)cid * 64 + i) * 128 + c] = qs[i * KQ + c] * egc[i] - accP;
        }
    }

    // M = keff^T @ k_cum ; U = keff^T @ v_new   (keff[i][a] = k[i][a] * egr[i])
    {
        int a = tid & 127, half = tid >> 7;
        float acc[64];
#pragma unroll
        for (int e = 0; e < 64; e++) acc[e] = 0.f;
        for (int i = 0; i < 64; i++) {
            float f = ks[i * KQ + a] * egr[i];
            const float* wr = ws + i * 256 + 128 + half * 64;
#pragma unroll
            for (int e = 0; e < 64; e++) acc[e] += f * wr[e];
        }
        for (int e = 0; e < 64; e++)
            Mout[((size_t)cid * 128 + a) * 128 + half * 64 + e] = acc[e];
#pragma unroll
        for (int e = 0; e < 64; e++) acc[e] = 0.f;
        for (int i = 0; i < 64; i++) {
            float f = ks[i * KQ + a] * egr[i];
            const float* wr = ws + i * 256 + half * 64;
#pragma unroll
            for (int e = 0; e < 64; e++) acc[e] += f * wr[e];
        }
        for (int e = 0; e < 64; e++)
            Uout[((size_t)cid * 128 + a) * 128 + half * 64 + e] = acc[e];
    }
    if (tid == 0) eglout[cid] = __expf(gc[63]);
}

// ---------------- Phase B: sequential scan over chunks, DV split ----------------
#define PB_SMEM ((128*128 + 64*128 + 128*16) * 4)

__global__ __launch_bounds__(256) void phaseB_kernel(const float* __restrict__ Pm,
        const float* __restrict__ Lm, const float* __restrict__ Mm,
        const float* __restrict__ Um, const float* __restrict__ eglv,
        float* __restrict__ core)
{
    extern __shared__ float sm[];
    float* Ms = sm;                 // 128 x 128
    float* Ps = Ms + 128 * 128;     // 64 x 128
    float* Ss = Ps + 64 * 128;      // 128 x 16 (S slice)

    int bh = blockIdx.x, gg = blockIdx.y;
    int b = bh >> 3, h = bh & 7;
    int tid = threadIdx.x;
    int c4g = tid & 3;              // 4-wide column group within the 16-col slice
    int a0 = tid >> 2;              // 0..63
    int c0 = gg * 16;

    for (int i = tid; i < 128 * 16; i += 256) Ss[i] = 0.f;
    __syncthreads();

    for (int n = 0; n < 64; n++) {
        size_t cid = (size_t)bh * 64 + n;
        const float4* Mg = (const float4*)(Mm + cid * 16384);
        float4* Ms4 = (float4*)Ms;
        for (int i = tid; i < 4096; i += 256) Ms4[i] = Mg[i];
        const float4* Pg = (const float4*)(Pm + cid * 8192);
        float4* Ps4 = (float4*)Ps;
        for (int i = tid; i < 2048; i += 256) Ps4[i] = Pg[i];
        __syncthreads();

        // out[i][c] = L[i][c] + sum_a P[i][a] * S[a][c]   (i = a0)
        {
            float4 acc = *(const float4*)(Lm + cid * 8192 + a0 * 128 + c0 + c4g * 4);
            for (int a = 0; a < 128; a++) {
                float p = Ps[a0 * 128 + a];
                float4 s = *(const float4*)(Ss + a * 16 + c4g * 4);
                acc.x += p * s.x; acc.y += p * s.y; acc.z += p * s.z; acc.w += p * s.w;
            }
            int t = n * 64 + a0;
            *(float4*)(core + (((size_t)(b * TT + t)) * 8 + h) * 128 + c0 + c4g * 4) = acc;
        }

        // S' = egl*S + U - M@S  (rows a0 and a0+64)
        float eg = eglv[cid];
        float4 s0 = *(const float4*)(Ss + a0 * 16 + c4g * 4);
        float4 s1 = *(const float4*)(Ss + (a0 + 64) * 16 + c4g * 4);
        float4 ns0 = *(const float4*)(Um + cid * 16384 + (size_t)a0 * 128 + c0 + c4g * 4);
        float4 ns1 = *(const float4*)(Um + cid * 16384 + (size_t)(a0 + 64) * 128 + c0 + c4g * 4);
        ns0.x += eg * s0.x; ns0.y += eg * s0.y; ns0.z += eg * s0.z; ns0.w += eg * s0.w;
        ns1.x += eg * s1.x; ns1.y += eg * s1.y; ns1.z += eg * s1.z; ns1.w += eg * s1.w;
        for (int ap = 0; ap < 128; ap++) {
            float4 s = *(const float4*)(Ss + ap * 16 + c4g * 4);
            float m0 = Ms[a0 * 128 + ap];
            float m1 = Ms[(a0 + 64) * 128 + ap];
            ns0.x -= m0 * s.x; ns0.y -= m0 * s.y; ns0.z -= m0 * s.z; ns0.w -= m0 * s.w;
            ns1.x -= m1 * s.x; ns1.y -= m1 * s.y; ns1.z -= m1 * s.z; ns1.w -= m1 * s.w;
        }
        __syncthreads();
        *(float4*)(Ss + a0 * 16 + c4g * 4) = ns0;
        *(float4*)(Ss + (a0 + 64) * 16 + c4g * 4) = ns1;
        __syncthreads();
    }
}

// ---------------- gated RMSNorm * silu(z) ---------------------------------------
__global__ __launch_bounds__(128) void norm_kernel(const float* __restrict__ core,
        const float* __restrict__ qkvz, const float* __restrict__ nw,
        float* __restrict__ hbuf)
{
    int bth = blockIdx.x;          // B*T*H, h fastest
    int d = threadIdx.x;
    float cv = core[(size_t)bth * 128 + d];
    float ss = cv * cv;
#pragma unroll
    for (int o = 16; o; o >>= 1) ss += __shfl_xor_sync(0xffffffffu, ss, o);
    __shared__ float red[4];
    if ((d & 31) == 0) red[d >> 5] = ss;
    __syncthreads();
    float tot = red[0] + red[1] + red[2] + red[3];
    float r = rsqrtf(tot * (1.f / 128.f) + 1e-6f);
    float zz = qkvz[(size_t)bth * 512 + 384 + d];
    float sz = zz / (1.f + __expf(-zz));
    hbuf[(size_t)bth * 128 + d] = nw[d] * cv * r * sz;
}

// ---------------- launch ---------------------------------------------------------
extern "C" void kernel_launch(void* const* d_in, const int* in_sizes, int n_in,
                              void* d_out, int out_size)
{
    (void)in_sizes; (void)n_in; (void)out_size;
    const float* x    = (const float*)d_in[0];
    const float* Wq   = (const float*)d_in[1];
    const float* Wba  = (const float*)d_in[2];
    const float* cw   = (const float*)d_in[3];
    const float* dtb  = (const float*)d_in[4];
    const float* Alog = (const float*)d_in[5];
    const float* nw   = (const float*)d_in[6];
    const float* Wout = (const float*)d_in[7];
    float* out = (float*)d_out;

    float *qkvz, *bab, *convb, *gb, *betab, *Pb, *Lb, *Mb, *Ub, *eglb, *coreb, *hb;
    cudaGetSymbolAddress((void**)&qkvz,  g_qkvz);
    cudaGetSymbolAddress((void**)&bab,   g_ba);
    cudaGetSymbolAddress((void**)&convb, g_conv);
    cudaGetSymbolAddress((void**)&gb,    g_g);
    cudaGetSymbolAddress((void**)&betab, g_beta);
    cudaGetSymbolAddress((void**)&Pb,    g_P);
    cudaGetSymbolAddress((void**)&Lb,    g_L);
    cudaGetSymbolAddress((void**)&Mb,    g_M);
    cudaGetSymbolAddress((void**)&Ub,    g_U);
    cudaGetSymbolAddress((void**)&eglb,  g_egl);
    cudaGetSymbolAddress((void**)&coreb, g_core);
    cudaGetSymbolAddress((void**)&hb,    g_hbuf);

    cudaFuncSetAttribute(phaseA_kernel, cudaFuncAttributeMaxDynamicSharedMemorySize, PA_SMEM);
    cudaFuncSetAttribute(phaseB_kernel, cudaFuncAttributeMaxDynamicSharedMemorySize, PB_SMEM);

    // 1. qkvz = x @ W_qkvz   (8192 x 1024 x 4096)
    dim3 g1(4096 / 128, 8192 / 128);
    sgemm128<<<g1, 256>>>(BB * TT, 4096, CC, x, Wq, qkvz);
    // 2. ba = x @ W_ba
    ba_kernel<<<BB * TT, 256>>>(x, Wba, bab);
    // 3. conv + silu
    conv_silu_kernel<<<(BB * TT * 3072) / 256, 256>>>(qkvz, cw, convb);
    // 4. g, beta
    gbeta_kernel<<<(BB * TT * NH) / 256, 256>>>(bab, dtb, Alog, gb, betab);
    // 5. phase A (per-chunk, fully parallel)
    phaseA_kernel<<<NCID, 256, PA_SMEM>>>(convb, gb, betab, Pb, Lb, Mb, Ub, eglb);
    // 6. phase B (sequential scan, 16 heads x 8 DV-groups)
    dim3 gB(16, 8);
    phaseB_kernel<<<gB, 256, PB_SMEM>>>(Pb, Lb, Mb, Ub, eglb, coreb);
    // 7. gated RMSNorm * silu(z)
    norm_kernel<<<BB * TT * NH, 128>>>(coreb, qkvz, nw, hb);
    // 8. final projection
    dim3 g2(1024 / 128, 8192 / 128);
    sgemm128<<<g2, 256>>>(BB * TT, 1024, CC, hb, Wout, out);
}

// round 2
// speedup vs baseline: 1.5744x; 1.5744x over previous
#include <cuda_runtime.h>
#include <math.h>

// Problem constants
#define BB 2
#define TT 4096
#define CC 1024
#define NH 8
#define DD 128
#define CHK 64
#define NCHUNK 64            // T / CHK
#define NCID 1024            // BB*NH*NCHUNK

// ---------------- scratch (device globals; no allocation allowed) ----------------
__device__ float g_qkvz[(size_t)BB*TT*4096];     // x @ W_qkvz      (B,T,8,512)
__device__ float g_ba[(size_t)BB*TT*16];         // x @ W_ba
__device__ float g_conv[(size_t)BB*TT*3072];     // conv+silu [q|k|v]
__device__ float g_g[(size_t)BB*TT*NH];
__device__ float g_beta[(size_t)BB*TT*NH];
__device__ float g_P[(size_t)NCID*64*128];       // qeff - attn@k_cum
__device__ float g_L[(size_t)NCID*64*128];       // attn@v_new
__device__ float g_M[(size_t)NCID*128*128];      // keff^T @ k_cum
__device__ float g_U[(size_t)NCID*128*128];      // keff^T @ v_new
__device__ float g_egl[NCID];                    // exp(g_last)
__device__ float g_core[(size_t)BB*TT*NH*DD];    // delta-rule output
__device__ float g_hbuf[(size_t)BB*TT*1024];     // post-norm, pre out-proj

// ---------------- tf32 helpers ---------------------------------------------------
__device__ __forceinline__ float tf32r(float x) {
    unsigned u;
    asm("cvt.rna.tf32.f32 %0, %1;" : "=r"(u) : "f"(x));
    return __uint_as_float(u);
}

#define MMA_TF32(C, Ar, Br)                                                    \
    asm volatile("mma.sync.aligned.m16n8k8.row.col.f32.tf32.tf32.f32 "         \
        "{%0,%1,%2,%3}, {%4,%5,%6,%7}, {%8,%9}, {%0,%1,%2,%3};"                \
        : "+f"((C)[0]), "+f"((C)[1]), "+f"((C)[2]), "+f"((C)[3])               \
        : "r"((Ar)[0]), "r"((Ar)[1]), "r"((Ar)[2]), "r"((Ar)[3]),              \
          "r"((Br)[0]), "r"((Br)[1]))

// ---------------- 3xTF32 tensor-core GEMM: C = A(MxK) @ B(KxN), row-major -------
// M,N multiples of 128; K multiple of 16. fp32-comparable accuracy via hi/lo split.
__global__ __launch_bounds__(256, 1) void tf32gemm128(int M, int N, int K,
        const float* __restrict__ A, const float* __restrict__ Bm, float* __restrict__ Cm)
{
    __shared__ float Ah[128][20], Al[128][20];     // [m][k], stride 20: conflict-free
    __shared__ float Bh[16][136], Bl[16][136];     // [k][n], stride 136: conflict-free

    int tid = threadIdx.x;
    int brow = blockIdx.y * 128, bcol = blockIdx.x * 128;
    int warp = tid >> 5, lane = tid & 31;
    int wm = (warp & 1) * 64, wn = (warp >> 1) * 32;
    int lr = lane >> 2, lc = lane & 3;

    float c[4][4][4];
#pragma unroll
    for (int mt = 0; mt < 4; mt++)
#pragma unroll
        for (int nt = 0; nt < 4; nt++)
#pragma unroll
            for (int e = 0; e < 4; e++) c[mt][nt][e] = 0.f;

    for (int k0 = 0; k0 < K; k0 += 16) {
        // load + split A tile (128x16)
#pragma unroll
        for (int u = 0; u < 2; u++) {
            int idx = tid + u * 256;
            int r = idx >> 2, cg = (idx & 3) * 4;
            float4 v = *(const float4*)(A + (size_t)(brow + r) * K + k0 + cg);
            float4 h, l;
            h.x = tf32r(v.x); l.x = tf32r(v.x - h.x);
            h.y = tf32r(v.y); l.y = tf32r(v.y - h.y);
            h.z = tf32r(v.z); l.z = tf32r(v.z - h.z);
            h.w = tf32r(v.w); l.w = tf32r(v.w - h.w);
            *(float4*)(&Ah[r][cg]) = h;
            *(float4*)(&Al[r][cg]) = l;
        }
        // load + split B tile (16x128)
#pragma unroll
        for (int u = 0; u < 2; u++) {
            int idx = tid + u * 256;
            int r = idx >> 5, cg = (idx & 31) * 4;
            float4 v = *(const float4*)(Bm + (size_t)(k0 + r) * N + bcol + cg);
            float4 h, l;
            h.x = tf32r(v.x); l.x = tf32r(v.x - h.x);
            h.y = tf32r(v.y); l.y = tf32r(v.y - h.y);
            h.z = tf32r(v.z); l.z = tf32r(v.z - h.z);
            h.w = tf32r(v.w); l.w = tf32r(v.w - h.w);
            *(float4*)(&Bh[r][cg]) = h;
            *(float4*)(&Bl[r][cg]) = l;
        }
        __syncthreads();

#pragma unroll
        for (int kk = 0; kk < 16; kk += 8) {
            unsigned ah[4][4], al[4][4], bh[4][2], bl[4][2];
#pragma unroll
            for (int mt = 0; mt < 4; mt++) {
                int r0 = wm + mt * 16 + lr;
                ah[mt][0] = __float_as_uint(Ah[r0][kk + lc]);
                ah[mt][1] = __float_as_uint(Ah[r0 + 8][kk + lc]);
                ah[mt][2] = __float_as_uint(Ah[r0][kk + lc + 4]);
                ah[mt][3] = __float_as_uint(Ah[r0 + 8][kk + lc + 4]);
                al[mt][0] = __float_as_uint(Al[r0][kk + lc]);
                al[mt][1] = __float_as_uint(Al[r0 + 8][kk + lc]);
                al[mt][2] = __float_as_uint(Al[r0][kk + lc + 4]);
                al[mt][3] = __float_as_uint(Al[r0 + 8][kk + lc + 4]);
            }
#pragma unroll
            for (int nt = 0; nt < 4; nt++) {
                int cn = wn + nt * 8 + lr;
                bh[nt][0] = __float_as_uint(Bh[kk + lc][cn]);
                bh[nt][1] = __float_as_uint(Bh[kk + lc + 4][cn]);
                bl[nt][0] = __float_as_uint(Bl[kk + lc][cn]);
                bl[nt][1] = __float_as_uint(Bl[kk + lc + 4][cn]);
            }
#pragma unroll
            for (int mt = 0; mt < 4; mt++)
#pragma unroll
                for (int nt = 0; nt < 4; nt++) {
                    MMA_TF32(c[mt][nt], ah[mt], bh[nt]);
                    MMA_TF32(c[mt][nt], al[mt], bh[nt]);
                    MMA_TF32(c[mt][nt], ah[mt], bl[nt]);
                }
        }
        __syncthreads();
    }

    // epilogue
#pragma unroll
    for (int mt = 0; mt < 4; mt++) {
        int r0 = brow + wm + mt * 16 + lr;
#pragma unroll
        for (int nt = 0; nt < 4; nt++) {
            int cn = bcol + wn + nt * 8 + 2 * lc;
            *(float2*)(Cm + (size_t)r0 * N + cn)       = make_float2(c[mt][nt][0], c[mt][nt][1]);
            *(float2*)(Cm + (size_t)(r0 + 8) * N + cn) = make_float2(c[mt][nt][2], c[mt][nt][3]);
        }
    }
}

// ---------------- ba = x @ W_ba (N = 16) ----------------------------------------
__global__ __launch_bounds__(256) void ba_kernel(const float* __restrict__ x,
        const float* __restrict__ Wba, float* __restrict__ out)
{
    int bt = blockIdx.x;
    __shared__ float xs[1024];
    const float* xrow = x + (size_t)bt * 1024;
    for (int i = threadIdx.x; i < 256; i += 256)
        ((float4*)xs)[i] = ((const float4*)xrow)[i];
    __syncthreads();
    int o = threadIdx.x >> 4, p = threadIdx.x & 15;
    float acc = 0.f;
    for (int k = p; k < 1024; k += 16) acc += xs[k] * Wba[(size_t)k * 16 + o];
    acc += __shfl_down_sync(0xffffffffu, acc, 8);
    acc += __shfl_down_sync(0xffffffffu, acc, 4);
    acc += __shfl_down_sync(0xffffffffu, acc, 2);
    acc += __shfl_down_sync(0xffffffffu, acc, 1);
    if (p == 0) out[(size_t)bt * 16 + o] = acc;
}

// ---------------- causal depthwise conv (K=4) + silu ----------------------------
__global__ __launch_bounds__(256) void conv_silu_kernel(const float* __restrict__ qkvz,
        const float* __restrict__ cw, float* __restrict__ out)
{
    int idx = blockIdx.x * 256 + threadIdx.x;        // over B*T*3072 (fits int)
    int ch = idx % 3072;
    int btrow = idx / 3072;                           // global row b*T + t
    int t = btrow & (TT - 1);
    int part = ch >> 10;                              // 0=q,1=k,2=v
    int hc = (ch & 1023) >> 7;
    int d = ch & 127;
    int po = (part == 0) ? 0 : (part == 1) ? 128 : 256;
    float acc = 0.f;
#pragma unroll
    for (int j = 0; j < 4; j++) {
        int tt2 = t - 3 + j;
        if (tt2 >= 0) {
            float v = qkvz[(((size_t)(btrow - 3 + j)) * 8 + hc) * 512 + po + d];
            acc += v * cw[ch * 4 + j];
        }
    }
    out[(size_t)idx] = acc / (1.f + __expf(-acc));    // silu
}

// ---------------- g, beta --------------------------------------------------------
__global__ __launch_bounds__(256) void gbeta_kernel(const float* __restrict__ ba,
        const float* __restrict__ dtb, const float* __restrict__ Alog,
        float* __restrict__ g, float* __restrict__ beta)
{
    int idx = blockIdx.x * 256 + threadIdx.x;         // B*T*8
    int h = idx & 7;
    int bt = idx >> 3;
    float bv = ba[(size_t)bt * 16 + h * 2];
    float av = ba[(size_t)bt * 16 + h * 2 + 1];
    beta[idx] = 1.f / (1.f + expf(-bv));
    float xx = av + dtb[h];
    float sp = (xx > 20.f) ? xx : log1pf(expf(xx));
    g[idx] = -expf(Alog[h]) * sp;
}

// ---------------- Phase A: per-chunk local operators ----------------------------
#define KQ 129                                       // padded row stride for q,k
#define PA_SMEM ((64*KQ*2 + 64*256 + 64*64 + 256) * 4)

__global__ __launch_bounds__(256) void phaseA_kernel(const float* __restrict__ conv,
        const float* __restrict__ gbuf, const float* __restrict__ betabuf,
        float* __restrict__ Pout, float* __restrict__ Lout,
        float* __restrict__ Mout, float* __restrict__ Uout, float* __restrict__ eglout)
{
    extern __shared__ float sm[];
    float* qs  = sm;                  // 64 x 129
    float* ks  = qs + 64 * KQ;        // 64 x 129
    float* ws  = ks + 64 * KQ;        // 64 x 256  [v*beta | k*beta*e^gc]
    float* As  = ws + 64 * 256;       // 64 x 64
    float* gc  = As + 64 * 64;        // 64
    float* egc = gc + 64;             // exp(gc)
    float* egr = egc + 64;            // exp(g_last - gc)
    float* bts = egr + 64;            // beta

    int cid = blockIdx.x;
    int n = cid & 63, bh = cid >> 6, h = bh & 7, b = bh >> 3;
    int tid = threadIdx.x;
    int t0 = n * 64;

    if (tid < 64) {
        int t = t0 + tid;
        gc[tid]  = gbuf[((size_t)(b * TT + t)) * 8 + h];
        bts[tid] = betabuf[((size_t)(b * TT + t)) * 8 + h];
    }
    __syncthreads();
    if (tid == 0) {
        float c = 0.f;
        for (int i = 0; i < 64; i++) { c += gc[i]; gc[i] = c; }
    }
    __syncthreads();
    if (tid < 64) {
        egc[tid] = __expf(gc[tid]);
        egr[tid] = __expf(gc[63] - gc[tid]);
    }
    __syncthreads();

    // load + l2norm q,k; init ws
    {
        int warp = tid >> 5, lane = tid & 31;
        for (int r = warp; r < 64; r += 8) {
            int t = t0 + r;
            const float* base = conv + ((size_t)(b * TT + t)) * 3072 + h * 128;
            float qv[4], kv[4];
            float ssq = 0.f, ssk = 0.f;
#pragma unroll
            for (int u = 0; u < 4; u++) {
                qv[u] = base[lane + u * 32];
                kv[u] = base[1024 + lane + u * 32];
                ssq += qv[u] * qv[u];
                ssk += kv[u] * kv[u];
            }
#pragma unroll
            for (int off = 16; off; off >>= 1) {
                ssq += __shfl_xor_sync(0xffffffffu, ssq, off);
                ssk += __shfl_xor_sync(0xffffffffu, ssk, off);
            }
            float rq = rsqrtf(ssq + 1e-6f) * 0.08838834764831845f;  // * DK^-0.5
            float rk = rsqrtf(ssk + 1e-6f);
            float bbv = bts[r], egv = egc[r];
#pragma unroll
            for (int u = 0; u < 4; u++) {
                int d = lane + u * 32;
                qs[r * KQ + d] = qv[u] * rq;
                float kn = kv[u] * rk;
                ks[r * KQ + d] = kn;
                ws[r * 256 + d]       = base[2048 + d] * bbv;   // v * beta
                ws[r * 256 + 128 + d] = kn * bbv * egv;          // k*beta*e^gc
            }
        }
    }
    __syncthreads();

    // A[i][j] = beta_i (k_i . k_j) exp(gc_i - gc_j), j < i (strict lower)
    {
        int i = tid >> 2, jg = tid & 3;
        for (int jj = 0; jj < 16; jj++) {
            int j = jg + jj * 4;
            float acc = 0.f;
            if (j < i) {
#pragma unroll 8
                for (int d = 0; d < 128; d++) acc += ks[i * KQ + d] * ks[j * KQ + d];
                acc *= bts[i] * __expf(gc[i] - gc[j]);
            }
            As[i * 64 + j] = acc;
        }
    }
    __syncthreads();

    // forward substitution: ws <- (I+A)^{-1} ws (each thread owns one column)
    {
        int c = tid;
        for (int i = 1; i < 64; i++) {
            float acc = 0.f;
            for (int j = 0; j < i; j++) acc += As[i * 64 + j] * ws[j * 256 + c];
            ws[i * 256 + c] -= acc;
        }
    }
    __syncthreads();

    // attn[i][j] = (q_i . k_j) exp(gc_i - gc_j), j <= i  (overwrite As)
    {
        int i = tid >> 2, jg = tid & 3;
        for (int jj = 0; jj < 16; jj++) {
            int j = jg + jj * 4;
            float acc = 0.f;
            if (j <= i) {
#pragma unroll 8
                for (int d = 0; d < 128; d++) acc += qs[i * KQ + d] * ks[j * KQ + d];
                acc *= __expf(gc[i] - gc[j]);
            }
            As[i * 64 + j] = acc;
        }
    }
    __syncthreads();

    // L = attn @ v_new ; P = q*e^gc - attn @ k_cum
    {
        int c = tid & 127, ig = tid >> 7;
        for (int r = 0; r < 32; r++) {
            int i = ig * 32 + r;
            float accL = 0.f, accP = 0.f;
            for (int j = 0; j <= i; j++) {
                float a = As[i * 64 + j];
                accL += a * ws[j * 256 + c];
                accP += a * ws[j * 256 + 128 + c];
            }
            Lout[((size_t)cid * 64 + i) * 128 + c] = accL;
            Pout[((size_t)cid * 64 + i) * 128 + c] = qs[i * KQ + c] * egc[i] - accP;
        }
    }

    // M = keff^T @ k_cum ; U = keff^T @ v_new   (keff[i][a] = k[i][a] * egr[i])
    {
        int a = tid & 127, half = tid >> 7;
        float acc[64];
#pragma unroll
        for (int e = 0; e < 64; e++) acc[e] = 0.f;
        for (int i = 0; i < 64; i++) {
            float f = ks[i * KQ + a] * egr[i];
            const float* wr = ws + i * 256 + 128 + half * 64;
#pragma unroll
            for (int e = 0; e < 64; e++) acc[e] += f * wr[e];
        }
        for (int e = 0; e < 64; e++)
            Mout[((size_t)cid * 128 + a) * 128 + half * 64 + e] = acc[e];
#pragma unroll
        for (int e = 0; e < 64; e++) acc[e] = 0.f;
        for (int i = 0; i < 64; i++) {
            float f = ks[i * KQ + a] * egr[i];
            const float* wr = ws + i * 256 + half * 64;
#pragma unroll
            for (int e = 0; e < 64; e++) acc[e] += f * wr[e];
        }
        for (int e = 0; e < 64; e++)
            Uout[((size_t)cid * 128 + a) * 128 + half * 64 + e] = acc[e];
    }
    if (tid == 0) eglout[cid] = __expf(gc[63]);
}

// ---------------- Phase B: sequential scan over chunks, DV split ----------------
#define PB_SMEM ((128*128 + 64*128 + 128*16) * 4)

__global__ __launch_bounds__(256) void phaseB_kernel(const float* __restrict__ Pm,
        const float* __restrict__ Lm, const float* __restrict__ Mm,
        const float* __restrict__ Um, const float* __restrict__ eglv,
        float* __restrict__ core)
{
    extern __shared__ float sm[];
    float* Ms = sm;                 // 128 x 128
    float* Ps = Ms + 128 * 128;     // 64 x 128
    float* Ss = Ps + 64 * 128;      // 128 x 16 (S slice)

    int bh = blockIdx.x, gg = blockIdx.y;
    int b = bh >> 3, h = bh & 7;
    int tid = threadIdx.x;
    int c4g = tid & 3;              // 4-wide column group within the 16-col slice
    int a0 = tid >> 2;              // 0..63
    int c0 = gg * 16;

    for (int i = tid; i < 128 * 16; i += 256) Ss[i] = 0.f;
    __syncthreads();

    for (int n = 0; n < 64; n++) {
        size_t cid = (size_t)bh * 64 + n;
        const float4* Mg = (const float4*)(Mm + cid * 16384);
        float4* Ms4 = (float4*)Ms;
        for (int i = tid; i < 4096; i += 256) Ms4[i] = Mg[i];
        const float4* Pg = (const float4*)(Pm + cid * 8192);
        float4* Ps4 = (float4*)Ps;
        for (int i = tid; i < 2048; i += 256) Ps4[i] = Pg[i];
        __syncthreads();

        // out[i][c] = L[i][c] + sum_a P[i][a] * S[a][c]   (i = a0)
        {
            float4 acc = *(const float4*)(Lm + cid * 8192 + a0 * 128 + c0 + c4g * 4);
            for (int a = 0; a < 128; a++) {
                float p = Ps[a0 * 128 + a];
                float4 s = *(const float4*)(Ss + a * 16 + c4g * 4);
                acc.x += p * s.x; acc.y += p * s.y; acc.z += p * s.z; acc.w += p * s.w;
            }
            int t = n * 64 + a0;
            *(float4*)(core + (((size_t)(b * TT + t)) * 8 + h) * 128 + c0 + c4g * 4) = acc;
        }

        // S' = egl*S + U - M@S  (rows a0 and a0+64)
        float eg = eglv[cid];
        float4 s0 = *(const float4*)(Ss + a0 * 16 + c4g * 4);
        float4 s1 = *(const float4*)(Ss + (a0 + 64) * 16 + c4g * 4);
        float4 ns0 = *(const float4*)(Um + cid * 16384 + (size_t)a0 * 128 + c0 + c4g * 4);
        float4 ns1 = *(const float4*)(Um + cid * 16384 + (size_t)(a0 + 64) * 128 + c0 + c4g * 4);
        ns0.x += eg * s0.x; ns0.y += eg * s0.y; ns0.z += eg * s0.z; ns0.w += eg * s0.w;
        ns1.x += eg * s1.x; ns1.y += eg * s1.y; ns1.z += eg * s1.z; ns1.w += eg * s1.w;
        for (int ap = 0; ap < 128; ap++) {
            float4 s = *(const float4*)(Ss + ap * 16 + c4g * 4);
            float m0 = Ms[a0 * 128 + ap];
            float m1 = Ms[(a0 + 64) * 128 + ap];
            ns0.x -= m0 * s.x; ns0.y -= m0 * s.y; ns0.z -= m0 * s.z; ns0.w -= m0 * s.w;
            ns1.x -= m1 * s.x; ns1.y -= m1 * s.y; ns1.z -= m1 * s.z; ns1.w -= m1 * s.w;
        }
        __syncthreads();
        *(float4*)(Ss + a0 * 16 + c4g * 4) = ns0;
        *(float4*)(Ss + (a0 + 64) * 16 + c4g * 4) = ns1;
        __syncthreads();
    }
}

// ---------------- gated RMSNorm * silu(z) ---------------------------------------
__global__ __launch_bounds__(128) void norm_kernel(const float* __restrict__ core,
        const float* __restrict__ qkvz, const float* __restrict__ nw,
        float* __restrict__ hbuf)
{
    int bth = blockIdx.x;          // B*T*H, h fastest
    int d = threadIdx.x;
    float cv = core[(size_t)bth * 128 + d];
    float ss = cv * cv;
#pragma unroll
    for (int o = 16; o; o >>= 1) ss += __shfl_xor_sync(0xffffffffu, ss, o);
    __shared__ float red[4];
    if ((d & 31) == 0) red[d >> 5] = ss;
    __syncthreads();
    float tot = red[0] + red[1] + red[2] + red[3];
    float r = rsqrtf(tot * (1.f / 128.f) + 1e-6f);
    float zz = qkvz[(size_t)bth * 512 + 384 + d];
    float sz = zz / (1.f + __expf(-zz));
    hbuf[(size_t)bth * 128 + d] = nw[d] * cv * r * sz;
}

// ---------------- launch ---------------------------------------------------------
extern "C" void kernel_launch(void* const* d_in, const int* in_sizes, int n_in,
                              void* d_out, int out_size)
{
    (void)in_sizes; (void)n_in; (void)out_size;
    const float* x    = (const float*)d_in[0];
    const float* Wq   = (const float*)d_in[1];
    const float* Wba  = (const float*)d_in[2];
    const float* cw   = (const float*)d_in[3];
    const float* dtb  = (const float*)d_in[4];
    const float* Alog = (const float*)d_in[5];
    const float* nw   = (const float*)d_in[6];
    const float* Wout = (const float*)d_in[7];
    float* out = (float*)d_out;

    float *qkvz, *bab, *convb, *gb, *betab, *Pb, *Lb, *Mb, *Ub, *eglb, *coreb, *hb;
    cudaGetSymbolAddress((void**)&qkvz,  g_qkvz);
    cudaGetSymbolAddress((void**)&bab,   g_ba);
    cudaGetSymbolAddress((void**)&convb, g_conv);
    cudaGetSymbolAddress((void**)&gb,    g_g);
    cudaGetSymbolAddress((void**)&betab, g_beta);
    cudaGetSymbolAddress((void**)&Pb,    g_P);
    cudaGetSymbolAddress((void**)&Lb,    g_L);
    cudaGetSymbolAddress((void**)&Mb,    g_M);
    cudaGetSymbolAddress((void**)&Ub,    g_U);
    cudaGetSymbolAddress((void**)&eglb,  g_egl);
    cudaGetSymbolAddress((void**)&coreb, g_core);
    cudaGetSymbolAddress((void**)&hb,    g_hbuf);

    cudaFuncSetAttribute(phaseA_kernel, cudaFuncAttributeMaxDynamicSharedMemorySize, PA_SMEM);
    cudaFuncSetAttribute(phaseB_kernel, cudaFuncAttributeMaxDynamicSharedMemorySize, PB_SMEM);

    // 1. qkvz = x @ W_qkvz   (8192 x 1024 x 4096), 3xTF32 tensor-core
    dim3 g1(4096 / 128, 8192 / 128);
    tf32gemm128<<<g1, 256>>>(BB * TT, 4096, CC, x, Wq, qkvz);
    // 2. ba = x @ W_ba
    ba_kernel<<<BB * TT, 256>>>(x, Wba, bab);
    // 3. conv + silu
    conv_silu_kernel<<<(BB * TT * 3072) / 256, 256>>>(qkvz, cw, convb);
    // 4. g, beta
    gbeta_kernel<<<(BB * TT * NH) / 256, 256>>>(bab, dtb, Alog, gb, betab);
    // 5. phase A (per-chunk, fully parallel)
    phaseA_kernel<<<NCID, 256, PA_SMEM>>>(convb, gb, betab, Pb, Lb, Mb, Ub, eglb);
    // 6. phase B (sequential scan, 16 heads x 8 DV-groups)
    dim3 gB(16, 8);
    phaseB_kernel<<<gB, 256, PB_SMEM>>>(Pb, Lb, Mb, Ub, eglb, coreb);
    // 7. gated RMSNorm * silu(z)
    norm_kernel<<<BB * TT * NH, 128>>>(coreb, qkvz, nw, hb);
    // 8. final projection, 3xTF32 tensor-core
    dim3 g2(1024 / 128, 8192 / 128);
    tf32gemm128<<<g2, 256>>>(BB * TT, 1024, CC, hb, Wout, out);
}

// round 3
// speedup vs baseline: 1.8010x; 1.1439x over previous
#include <cuda_runtime.h>
#include <math.h>

// Problem constants
#define BB 2
#define TT 4096
#define CC 1024
#define NH 8
#define DD 128
#define CHK 64
#define NCHUNK 64            // T / CHK
#define NCID 1024            // BB*NH*NCHUNK

// ---------------- scratch (device globals; no allocation allowed) ----------------
__device__ float g_qkvz[(size_t)BB*TT*4096];     // x @ W_qkvz      (B,T,8,512)
__device__ float g_ba[(size_t)BB*TT*16];         // x @ W_ba
__device__ float g_conv[(size_t)BB*TT*3072];     // conv+silu [q|k|v]
__device__ float g_g[(size_t)BB*TT*NH];
__device__ float g_beta[(size_t)BB*TT*NH];
__device__ float g_P[(size_t)NCID*64*128];       // qeff - attn@k_cum
__device__ float g_L[(size_t)NCID*64*128];       // attn@v_new
__device__ float g_M[(size_t)NCID*128*128];      // keff^T @ k_cum
__device__ float g_U[(size_t)NCID*128*128];      // keff^T @ v_new
__device__ float g_egl[NCID];                    // exp(g_last)
__device__ float g_core[(size_t)BB*TT*NH*DD];    // delta-rule output
__device__ float g_hbuf[(size_t)BB*TT*1024];     // post-norm, pre out-proj

// ---------------- tf32 helpers ---------------------------------------------------
__device__ __forceinline__ float tf32r(float x) {
    unsigned u;
    asm("cvt.rna.tf32.f32 %0, %1;" : "=r"(u) : "f"(x));
    return __uint_as_float(u);
}

#define MMA_TF32(C, Ar, Br)                                                    \
    asm volatile("mma.sync.aligned.m16n8k8.row.col.f32.tf32.tf32.f32 "         \
        "{%0,%1,%2,%3}, {%4,%5,%6,%7}, {%8,%9}, {%0,%1,%2,%3};"                \
        : "+f"((C)[0]), "+f"((C)[1]), "+f"((C)[2]), "+f"((C)[3])               \
        : "r"((Ar)[0]), "r"((Ar)[1]), "r"((Ar)[2]), "r"((Ar)[3]),              \
          "r"((Br)[0]), "r"((Br)[1]))

// ---------------- 3xTF32 tensor-core GEMM: C = A(MxK) @ B(KxN), row-major -------
__global__ __launch_bounds__(256, 1) void tf32gemm128(int M, int N, int K,
        const float* __restrict__ A, const float* __restrict__ Bm, float* __restrict__ Cm)
{
    __shared__ float Ah[128][20], Al[128][20];     // [m][k], stride 20: conflict-free
    __shared__ float Bh[16][136], Bl[16][136];     // [k][n], stride 136: conflict-free

    int tid = threadIdx.x;
    int brow = blockIdx.y * 128, bcol = blockIdx.x * 128;
    int warp = tid >> 5, lane = tid & 31;
    int wm = (warp & 1) * 64, wn = (warp >> 1) * 32;
    int lr = lane >> 2, lc = lane & 3;

    float c[4][4][4];
#pragma unroll
    for (int mt = 0; mt < 4; mt++)
#pragma unroll
        for (int nt = 0; nt < 4; nt++)
#pragma unroll
            for (int e = 0; e < 4; e++) c[mt][nt][e] = 0.f;

    for (int k0 = 0; k0 < K; k0 += 16) {
#pragma unroll
        for (int u = 0; u < 2; u++) {
            int idx = tid + u * 256;
            int r = idx >> 2, cg = (idx & 3) * 4;
            float4 v = *(const float4*)(A + (size_t)(brow + r) * K + k0 + cg);
            float4 h, l;
            h.x = tf32r(v.x); l.x = tf32r(v.x - h.x);
            h.y = tf32r(v.y); l.y = tf32r(v.y - h.y);
            h.z = tf32r(v.z); l.z = tf32r(v.z - h.z);
            h.w = tf32r(v.w); l.w = tf32r(v.w - h.w);
            *(float4*)(&Ah[r][cg]) = h;
            *(float4*)(&Al[r][cg]) = l;
        }
#pragma unroll
        for (int u = 0; u < 2; u++) {
            int idx = tid + u * 256;
            int r = idx >> 5, cg = (idx & 31) * 4;
            float4 v = *(const float4*)(Bm + (size_t)(k0 + r) * N + bcol + cg);
            float4 h, l;
            h.x = tf32r(v.x); l.x = tf32r(v.x - h.x);
            h.y = tf32r(v.y); l.y = tf32r(v.y - h.y);
            h.z = tf32r(v.z); l.z = tf32r(v.z - h.z);
            h.w = tf32r(v.w); l.w = tf32r(v.w - h.w);
            *(float4*)(&Bh[r][cg]) = h;
            *(float4*)(&Bl[r][cg]) = l;
        }
        __syncthreads();

#pragma unroll
        for (int kk = 0; kk < 16; kk += 8) {
            unsigned ah[4][4], al[4][4], bh[4][2], bl[4][2];
#pragma unroll
            for (int mt = 0; mt < 4; mt++) {
                int r0 = wm + mt * 16 + lr;
                ah[mt][0] = __float_as_uint(Ah[r0][kk + lc]);
                ah[mt][1] = __float_as_uint(Ah[r0 + 8][kk + lc]);
                ah[mt][2] = __float_as_uint(Ah[r0][kk + lc + 4]);
                ah[mt][3] = __float_as_uint(Ah[r0 + 8][kk + lc + 4]);
                al[mt][0] = __float_as_uint(Al[r0][kk + lc]);
                al[mt][1] = __float_as_uint(Al[r0 + 8][kk + lc]);
                al[mt][2] = __float_as_uint(Al[r0][kk + lc + 4]);
                al[mt][3] = __float_as_uint(Al[r0 + 8][kk + lc + 4]);
            }
#pragma unroll
            for (int nt = 0; nt < 4; nt++) {
                int cn = wn + nt * 8 + lr;
                bh[nt][0] = __float_as_uint(Bh[kk + lc][cn]);
                bh[nt][1] = __float_as_uint(Bh[kk + lc + 4][cn]);
                bl[nt][0] = __float_as_uint(Bl[kk + lc][cn]);
                bl[nt][1] = __float_as_uint(Bl[kk + lc + 4][cn]);
            }
#pragma unroll
            for (int mt = 0; mt < 4; mt++)
#pragma unroll
                for (int nt = 0; nt < 4; nt++) {
                    MMA_TF32(c[mt][nt], ah[mt], bh[nt]);
                    MMA_TF32(c[mt][nt], al[mt], bh[nt]);
                    MMA_TF32(c[mt][nt], ah[mt], bl[nt]);
                }
        }
        __syncthreads();
    }

#pragma unroll
    for (int mt = 0; mt < 4; mt++) {
        int r0 = brow + wm + mt * 16 + lr;
#pragma unroll
        for (int nt = 0; nt < 4; nt++) {
            int cn = bcol + wn + nt * 8 + 2 * lc;
            *(float2*)(Cm + (size_t)r0 * N + cn)       = make_float2(c[mt][nt][0], c[mt][nt][1]);
            *(float2*)(Cm + (size_t)(r0 + 8) * N + cn) = make_float2(c[mt][nt][2], c[mt][nt][3]);
        }
    }
}

// ---------------- ba = x @ W_ba (N = 16) ----------------------------------------
__global__ __launch_bounds__(256) void ba_kernel(const float* __restrict__ x,
        const float* __restrict__ Wba, float* __restrict__ out)
{
    int bt = blockIdx.x;
    __shared__ float xs[1024];
    const float* xrow = x + (size_t)bt * 1024;
    for (int i = threadIdx.x; i < 256; i += 256)
        ((float4*)xs)[i] = ((const float4*)xrow)[i];
    __syncthreads();
    int o = threadIdx.x >> 4, p = threadIdx.x & 15;
    float acc = 0.f;
    for (int k = p; k < 1024; k += 16) acc += xs[k] * Wba[(size_t)k * 16 + o];
    acc += __shfl_down_sync(0xffffffffu, acc, 8);
    acc += __shfl_down_sync(0xffffffffu, acc, 4);
    acc += __shfl_down_sync(0xffffffffu, acc, 2);
    acc += __shfl_down_sync(0xffffffffu, acc, 1);
    if (p == 0) out[(size_t)bt * 16 + o] = acc;
}

// ---------------- causal depthwise conv (K=4) + silu ----------------------------
__global__ __launch_bounds__(256) void conv_silu_kernel(const float* __restrict__ qkvz,
        const float* __restrict__ cw, float* __restrict__ out)
{
    int idx = blockIdx.x * 256 + threadIdx.x;
    int ch = idx % 3072;
    int btrow = idx / 3072;
    int t = btrow & (TT - 1);
    int part = ch >> 10;
    int hc = (ch & 1023) >> 7;
    int d = ch & 127;
    int po = (part == 0) ? 0 : (part == 1) ? 128 : 256;
    float acc = 0.f;
#pragma unroll
    for (int j = 0; j < 4; j++) {
        int tt2 = t - 3 + j;
        if (tt2 >= 0) {
            float v = qkvz[(((size_t)(btrow - 3 + j)) * 8 + hc) * 512 + po + d];
            acc += v * cw[ch * 4 + j];
        }
    }
    out[(size_t)idx] = acc / (1.f + __expf(-acc));
}

// ---------------- g, beta --------------------------------------------------------
__global__ __launch_bounds__(256) void gbeta_kernel(const float* __restrict__ ba,
        const float* __restrict__ dtb, const float* __restrict__ Alog,
        float* __restrict__ g, float* __restrict__ beta)
{
    int idx = blockIdx.x * 256 + threadIdx.x;
    int h = idx & 7;
    int bt = idx >> 3;
    float bv = ba[(size_t)bt * 16 + h * 2];
    float av = ba[(size_t)bt * 16 + h * 2 + 1];
    beta[idx] = 1.f / (1.f + expf(-bv));
    float xx = av + dtb[h];
    float sp = (xx > 20.f) ? xx : log1pf(expf(xx));
    g[idx] = -expf(Alog[h]) * sp;
}

// ---------------- Phase A: per-chunk local operators (register-tiled) -----------
#define KST 68                                  // transposed stride for kst/qst
#define PA_SMEM ((128*KST*2 + 64*256 + 64*64 + 256) * 4)

__global__ __launch_bounds__(256) void phaseA_kernel(const float* __restrict__ conv,
        const float* __restrict__ gbuf, const float* __restrict__ betabuf,
        float* __restrict__ Pout, float* __restrict__ Lout,
        float* __restrict__ Mout, float* __restrict__ Uout, float* __restrict__ eglout)
{
    extern __shared__ float sm[];
    float* kst = sm;                  // [128][KST]  kst[d*KST + i] = k_norm[i][d]
    float* qst = kst + 128 * KST;     // [128][KST]  q_norm (incl DK^-0.5)
    float* ws  = qst + 128 * KST;     // [64][256]   [v*beta | k*beta*e^gc] -> v_new|k_cum
    float* As  = ws + 64 * 256;       // [64][64]
    float* gc  = As + 64 * 64;        // 64
    float* egc = gc + 64;
    float* egr = egc + 64;
    float* bts = egr + 64;

    int cid = blockIdx.x;
    int n = cid & 63, bh = cid >> 6, h = bh & 7, b = bh >> 3;
    int tid = threadIdx.x;
    int warp = tid >> 5, lane = tid & 31;
    int t0 = n * 64;

    if (tid < 64) {
        int t = t0 + tid;
        gc[tid]  = gbuf[((size_t)(b * TT + t)) * 8 + h];
        bts[tid] = betabuf[((size_t)(b * TT + t)) * 8 + h];
    }
    __syncthreads();
    // parallel inclusive scan of gc (64 elems)
#pragma unroll
    for (int off = 1; off < 64; off <<= 1) {
        float v = 0.f;
        if (tid < 64 && tid >= off) v = gc[tid - off];
        __syncthreads();
        if (tid < 64 && tid >= off) gc[tid] += v;
        __syncthreads();
    }
    if (tid < 64) {
        egc[tid] = __expf(gc[tid]);
        egr[tid] = __expf(gc[63] - gc[tid]);
    }
    __syncthreads();

    // load + l2norm q,k -> transposed smem; init ws
    for (int r = warp; r < 64; r += 8) {
        int t = t0 + r;
        const float* base = conv + ((size_t)(b * TT + t)) * 3072 + h * 128;
        float qv[4], kv[4];
        float ssq = 0.f, ssk = 0.f;
#pragma unroll
        for (int u = 0; u < 4; u++) {
            qv[u] = base[lane + u * 32];
            kv[u] = base[1024 + lane + u * 32];
            ssq += qv[u] * qv[u];
            ssk += kv[u] * kv[u];
        }
#pragma unroll
        for (int off = 16; off; off >>= 1) {
            ssq += __shfl_xor_sync(0xffffffffu, ssq, off);
            ssk += __shfl_xor_sync(0xffffffffu, ssk, off);
        }
        float rq = rsqrtf(ssq + 1e-6f) * 0.08838834764831845f;  // * DK^-0.5
        float rk = rsqrtf(ssk + 1e-6f);
        float bbv = bts[r], egv = egc[r];
#pragma unroll
        for (int u = 0; u < 4; u++) {
            int d = lane + u * 32;
            qst[d * KST + r] = qv[u] * rq;
            float kn = kv[u] * rk;
            kst[d * KST + r] = kn;
            ws[r * 256 + d]       = base[2048 + d] * bbv;   // v * beta
            ws[r * 256 + 128 + d] = kn * bbv * egv;          // k*beta*e^gc
        }
    }
    __syncthreads();

    int ti = tid >> 4, tj = tid & 15;        // 16x16 thread grid for 64x64 matrices

    // A[i][j] = beta_i (k_i . k_j) exp(gc_i - gc_j), j < i; else 0
    {
        float acc[4][4];
#pragma unroll
        for (int r = 0; r < 4; r++)
#pragma unroll
            for (int s = 0; s < 4; s++) acc[r][s] = 0.f;
        const float* ka = kst + ti * 4;
        const float* kb = kst + tj * 4;
#pragma unroll 4
        for (int d = 0; d < 128; d++) {
            float4 a = *(const float4*)(ka + d * KST);
            float4 bq = *(const float4*)(kb + d * KST);
            float ra[4] = {a.x, a.y, a.z, a.w};
            float rb[4] = {bq.x, bq.y, bq.z, bq.w};
#pragma unroll
            for (int r = 0; r < 4; r++)
#pragma unroll
                for (int s = 0; s < 4; s++) acc[r][s] += ra[r] * rb[s];
        }
#pragma unroll
        for (int r = 0; r < 4; r++) {
            int i = ti * 4 + r;
#pragma unroll
            for (int s = 0; s < 4; s++) {
                int j = tj * 4 + s;
                As[i * 64 + j] = (j < i) ? acc[r][s] * bts[i] * __expf(gc[i] - gc[j]) : 0.f;
            }
        }
    }
    __syncthreads();

    // blocked forward substitution: ws <- (I+A)^{-1} ws
    for (int blk = 0; blk < 4; blk++) {
        if (blk) {
            int tr = tid >> 7, tc = tid & 127;        // 2 row-halves x 128 col-pairs
            float acc[8][2];
#pragma unroll
            for (int r = 0; r < 8; r++) { acc[r][0] = 0.f; acc[r][1] = 0.f; }
            for (int j = 0; j < blk * 16; j++) {
                float2 wv = *(const float2*)(ws + j * 256 + tc * 2);
#pragma unroll
                for (int r = 0; r < 8; r++) {
                    float a = As[(blk * 16 + tr * 8 + r) * 64 + j];
                    acc[r][0] += a * wv.x;
                    acc[r][1] += a * wv.y;
                }
            }
#pragma unroll
            for (int r = 0; r < 8; r++) {
                float* w = ws + (blk * 16 + tr * 8 + r) * 256 + tc * 2;
                w[0] -= acc[r][0];
                w[1] -= acc[r][1];
            }
            __syncthreads();
        }
        {   // serial within block; each thread owns one column
            int c = tid;
            int i0 = blk * 16;
            for (int i = i0 + 1; i < i0 + 16; i++) {
                float acc = 0.f;
                for (int j = i0; j < i; j++) acc += As[i * 64 + j] * ws[j * 256 + c];
                ws[i * 256 + c] -= acc;
            }
        }
        __syncthreads();
    }

    // attn[i][j] = (q_i . k_j) exp(gc_i - gc_j), j <= i; else 0 (overwrite As)
    {
        float acc[4][4];
#pragma unroll
        for (int r = 0; r < 4; r++)
#pragma unroll
            for (int s = 0; s < 4; s++) acc[r][s] = 0.f;
        const float* qa = qst + ti * 4;
        const float* kb = kst + tj * 4;
#pragma unroll 4
        for (int d = 0; d < 128; d++) {
            float4 a = *(const float4*)(qa + d * KST);
            float4 bq = *(const float4*)(kb + d * KST);
            float ra[4] = {a.x, a.y, a.z, a.w};
            float rb[4] = {bq.x, bq.y, bq.z, bq.w};
#pragma unroll
            for (int r = 0; r < 4; r++)
#pragma unroll
                for (int s = 0; s < 4; s++) acc[r][s] += ra[r] * rb[s];
        }
#pragma unroll
        for (int r = 0; r < 4; r++) {
            int i = ti * 4 + r;
#pragma unroll
            for (int s = 0; s < 4; s++) {
                int j = tj * 4 + s;
                As[i * 64 + j] = (j <= i) ? acc[r][s] * __expf(gc[i] - gc[j]) : 0.f;
            }
        }
    }
    __syncthreads();

    // [L | attn@k_cum] = attn @ ws ;  P = q*e^gc - attn@k_cum
    {
        int tr = warp;                 // 8 row-groups of 8
        int tc = lane;                 // 32 col-groups of 8
        float acc[8][8];
#pragma unroll
        for (int r = 0; r < 8; r++)
#pragma unroll
            for (int u = 0; u < 8; u++) acc[r][u] = 0.f;
        int jmax = tr * 8 + 8;         // causal: attn[i][j]=0 beyond i
        for (int j = 0; j < jmax; j++) {
            float av[8];
#pragma unroll
            for (int r = 0; r < 8; r++) av[r] = As[(tr * 8 + r) * 64 + j];
            float4 w0 = *(const float4*)(ws + j * 256 + tc * 8);
            float4 w1 = *(const float4*)(ws + j * 256 + tc * 8 + 4);
            float rb[8] = {w0.x, w0.y, w0.z, w0.w, w1.x, w1.y, w1.z, w1.w};
#pragma unroll
            for (int r = 0; r < 8; r++)
#pragma unroll
                for (int u = 0; u < 8; u++) acc[r][u] += av[r] * rb[u];
        }
        if (tc < 16) {
#pragma unroll
            for (int r = 0; r < 8; r++) {
                int i = tr * 8 + r;
                float* dst = Lout + ((size_t)cid * 64 + i) * 128 + tc * 8;
                *(float4*)(dst)     = make_float4(acc[r][0], acc[r][1], acc[r][2], acc[r][3]);
                *(float4*)(dst + 4) = make_float4(acc[r][4], acc[r][5], acc[r][6], acc[r][7]);
            }
        } else {
            int c0 = tc * 8 - 128;
#pragma unroll
            for (int r = 0; r < 8; r++) {
                int i = tr * 8 + r;
                float eg = egc[i];
                float v[8];
#pragma unroll
                for (int u = 0; u < 8; u++)
                    v[u] = qst[(c0 + u) * KST + i] * eg - acc[r][u];
                float* dst = Pout + ((size_t)cid * 64 + i) * 128 + c0;
                *(float4*)(dst)     = make_float4(v[0], v[1], v[2], v[3]);
                *(float4*)(dst + 4) = make_float4(v[4], v[5], v[6], v[7]);
            }
        }
    }

    // M = keff^T @ k_cum ; U = keff^T @ v_new ; keff[i][a] = k[i][a]*egr[i]
    {
        int ta = tid >> 4;             // 16 groups of 8 a-rows
        int te = tid & 15;             // 16 groups of 8 e-cols
#pragma unroll
        for (int pass = 0; pass < 2; pass++) {   // 0: U (v_new), 1: M (k_cum)
            float acc[8][8];
#pragma unroll
            for (int r = 0; r < 8; r++)
#pragma unroll
                for (int u = 0; u < 8; u++) acc[r][u] = 0.f;
            for (int i = 0; i < 64; i++) {
                float er = egr[i];
                float av[8];
#pragma unroll
                for (int r = 0; r < 8; r++) av[r] = kst[(ta * 8 + r) * KST + i] * er;
                float4 w0 = *(const float4*)(ws + i * 256 + pass * 128 + te * 8);
                float4 w1 = *(const float4*)(ws + i * 256 + pass * 128 + te * 8 + 4);
                float rb[8] = {w0.x, w0.y, w0.z, w0.w, w1.x, w1.y, w1.z, w1.w};
#pragma unroll
                for (int r = 0; r < 8; r++)
#pragma unroll
                    for (int u = 0; u < 8; u++) acc[r][u] += av[r] * rb[u];
            }
            float* dstb = pass ? Mout : Uout;
#pragma unroll
            for (int r = 0; r < 8; r++) {
                float* dst = dstb + ((size_t)cid * 128 + ta * 8 + r) * 128 + te * 8;
                *(float4*)(dst)     = make_float4(acc[r][0], acc[r][1], acc[r][2], acc[r][3]);
                *(float4*)(dst + 4) = make_float4(acc[r][4], acc[r][5], acc[r][6], acc[r][7]);
            }
        }
    }
    if (tid == 0) eglout[cid] = __expf(gc[63]);
}

// ---------------- Phase B: sequential scan over chunks, DV split ----------------
#define PB_SMEM ((128*128 + 64*128 + 128*16) * 4)

__global__ __launch_bounds__(256) void phaseB_kernel(const float* __restrict__ Pm,
        const float* __restrict__ Lm, const float* __restrict__ Mm,
        const float* __restrict__ Um, const float* __restrict__ eglv,
        float* __restrict__ core)
{
    extern __shared__ float sm[];
    float* Ms = sm;                 // 128 x 128
    float* Ps = Ms + 128 * 128;     // 64 x 128
    float* Ss = Ps + 64 * 128;      // 128 x 16 (S slice)

    int bh = blockIdx.x, gg = blockIdx.y;
    int b = bh >> 3, h = bh & 7;
    int tid = threadIdx.x;
    int c4g = tid & 3;
    int a0 = tid >> 2;
    int c0 = gg * 16;

    for (int i = tid; i < 128 * 16; i += 256) Ss[i] = 0.f;
    __syncthreads();

    for (int n = 0; n < 64; n++) {
        size_t cid = (size_t)bh * 64 + n;
        const float4* Mg = (const float4*)(Mm + cid * 16384);
        float4* Ms4 = (float4*)Ms;
        for (int i = tid; i < 4096; i += 256) Ms4[i] = Mg[i];
        const float4* Pg = (const float4*)(Pm + cid * 8192);
        float4* Ps4 = (float4*)Ps;
        for (int i = tid; i < 2048; i += 256) Ps4[i] = Pg[i];
        __syncthreads();

        {
            float4 acc = *(const float4*)(Lm + cid * 8192 + a0 * 128 + c0 + c4g * 4);
            for (int a = 0; a < 128; a++) {
                float p = Ps[a0 * 128 + a];
                float4 s = *(const float4*)(Ss + a * 16 + c4g * 4);
                acc.x += p * s.x; acc.y += p * s.y; acc.z += p * s.z; acc.w += p * s.w;
            }
            int t = n * 64 + a0;
            *(float4*)(core + (((size_t)(b * TT + t)) * 8 + h) * 128 + c0 + c4g * 4) = acc;
        }

        float eg = eglv[cid];
        float4 s0 = *(const float4*)(Ss + a0 * 16 + c4g * 4);
        float4 s1 = *(const float4*)(Ss + (a0 + 64) * 16 + c4g * 4);
        float4 ns0 = *(const float4*)(Um + cid * 16384 + (size_t)a0 * 128 + c0 + c4g * 4);
        float4 ns1 = *(const float4*)(Um + cid * 16384 + (size_t)(a0 + 64) * 128 + c0 + c4g * 4);
        ns0.x += eg * s0.x; ns0.y += eg * s0.y; ns0.z += eg * s0.z; ns0.w += eg * s0.w;
        ns1.x += eg * s1.x; ns1.y += eg * s1.y; ns1.z += eg * s1.z; ns1.w += eg * s1.w;
        for (int ap = 0; ap < 128; ap++) {
            float4 s = *(const float4*)(Ss + ap * 16 + c4g * 4);
            float m0 = Ms[a0 * 128 + ap];
            float m1 = Ms[(a0 + 64) * 128 + ap];
            ns0.x -= m0 * s.x; ns0.y -= m0 * s.y; ns0.z -= m0 * s.z; ns0.w -= m0 * s.w;
            ns1.x -= m1 * s.x; ns1.y -= m1 * s.y; ns1.z -= m1 * s.z; ns1.w -= m1 * s.w;
        }
        __syncthreads();
        *(float4*)(Ss + a0 * 16 + c4g * 4) = ns0;
        *(float4*)(Ss + (a0 + 64) * 16 + c4g * 4) = ns1;
        __syncthreads();
    }
}

// ---------------- gated RMSNorm * silu(z) ---------------------------------------
__global__ __launch_bounds__(128) void norm_kernel(const float* __restrict__ core,
        const float* __restrict__ qkvz, const float* __restrict__ nw,
        float* __restrict__ hbuf)
{
    int bth = blockIdx.x;
    int d = threadIdx.x;
    float cv = core[(size_t)bth * 128 + d];
    float ss = cv * cv;
#pragma unroll
    for (int o = 16; o; o >>= 1) ss += __shfl_xor_sync(0xffffffffu, ss, o);
    __shared__ float red[4];
    if ((d & 31) == 0) red[d >> 5] = ss;
    __syncthreads();
    float tot = red[0] + red[1] + red[2] + red[3];
    float r = rsqrtf(tot * (1.f / 128.f) + 1e-6f);
    float zz = qkvz[(size_t)bth * 512 + 384 + d];
    float sz = zz / (1.f + __expf(-zz));
    hbuf[(size_t)bth * 128 + d] = nw[d] * cv * r * sz;
}

// ---------------- launch ---------------------------------------------------------
extern "C" void kernel_launch(void* const* d_in, const int* in_sizes, int n_in,
                              void* d_out, int out_size)
{
    (void)in_sizes; (void)n_in; (void)out_size;
    const float* x    = (const float*)d_in[0];
    const float* Wq   = (const float*)d_in[1];
    const float* Wba  = (const float*)d_in[2];
    const float* cw   = (const float*)d_in[3];
    const float* dtb  = (const float*)d_in[4];
    const float* Alog = (const float*)d_in[5];
    const float* nw   = (const float*)d_in[6];
    const float* Wout = (const float*)d_in[7];
    float* out = (float*)d_out;

    float *qkvz, *bab, *convb, *gb, *betab, *Pb, *Lb, *Mb, *Ub, *eglb, *coreb, *hb;
    cudaGetSymbolAddress((void**)&qkvz,  g_qkvz);
    cudaGetSymbolAddress((void**)&bab,   g_ba);
    cudaGetSymbolAddress((void**)&convb, g_conv);
    cudaGetSymbolAddress((void**)&gb,    g_g);
    cudaGetSymbolAddress((void**)&betab, g_beta);
    cudaGetSymbolAddress((void**)&Pb,    g_P);
    cudaGetSymbolAddress((void**)&Lb,    g_L);
    cudaGetSymbolAddress((void**)&Mb,    g_M);
    cudaGetSymbolAddress((void**)&Ub,    g_U);
    cudaGetSymbolAddress((void**)&eglb,  g_egl);
    cudaGetSymbolAddress((void**)&coreb, g_core);
    cudaGetSymbolAddress((void**)&hb,    g_hbuf);

    cudaFuncSetAttribute(phaseA_kernel, cudaFuncAttributeMaxDynamicSharedMemorySize, PA_SMEM);
    cudaFuncSetAttribute(phaseB_kernel, cudaFuncAttributeMaxDynamicSharedMemorySize, PB_SMEM);

    dim3 g1(4096 / 128, 8192 / 128);
    tf32gemm128<<<g1, 256>>>(BB * TT, 4096, CC, x, Wq, qkvz);
    ba_kernel<<<BB * TT, 256>>>(x, Wba, bab);
    conv_silu_kernel<<<(BB * TT * 3072) / 256, 256>>>(qkvz, cw, convb);
    gbeta_kernel<<<(BB * TT * NH) / 256, 256>>>(bab, dtb, Alog, gb, betab);
    phaseA_kernel<<<NCID, 256, PA_SMEM>>>(convb, gb, betab, Pb, Lb, Mb, Ub, eglb);
    dim3 gB(16, 8);
    phaseB_kernel<<<gB, 256, PB_SMEM>>>(Pb, Lb, Mb, Ub, eglb, coreb);
    norm_kernel<<<BB * TT * NH, 128>>>(coreb, qkvz, nw, hb);
    dim3 g2(1024 / 128, 8192 / 128);
    tf32gemm128<<<g2, 256>>>(BB * TT, 1024, CC, hb, Wout, out);
}